// round 14
// baseline (speedup 1.0000x reference)
#include <cuda_runtime.h>
#include <cuda_fp16.h>
#include <cstdint>

#define N_NODES_MAX 100000
#define D_FEAT 128

// u32 packed accumulator: {count:8 | sum_fx:24}, sum in 2^-13 units.
//   max degree ~120 << 255; max sum_fx ~120*7.8*8192 = 7.7M << 2^24.
#define FP_SCALE   8192.0f
#define FP_INV     (1.0f/8192.0f)
#define CNT_ONE    (1u << 24)
#define SUM_MASK   ((1u << 24) - 1)

#define EDGE_TPB   1024
#define EDGE_GRID  148
#define SMEM_BYTES (N_NODES_MAX * 2)   // 200,000 B fp16 pos table

// Scratch (static __device__ arrays — no allocation per harness rules)
__device__ float                g_pos[N_NODES_MAX];
__device__ __align__(16) __half g_posh[N_NODES_MAX];
__device__ unsigned int         g_acc[N_NODES_MAX];

// Kernel 1: compact pos column + zero accumulators. 4 nodes/thread, loads
// batched up front (MLP=4) — was 27% DRAM at MLP=1.
__global__ void k_init(const float* __restrict__ h, int n_nodes) {
    int i0 = (blockIdx.x * blockDim.x + threadIdx.x) * 4;
    if (i0 + 3 < n_nodes) {
        float v0 = h[(size_t)(i0 + 0) * D_FEAT];
        float v1 = h[(size_t)(i0 + 1) * D_FEAT];
        float v2 = h[(size_t)(i0 + 2) * D_FEAT];
        float v3 = h[(size_t)(i0 + 3) * D_FEAT];
        g_pos[i0 + 0] = v0; g_pos[i0 + 1] = v1;
        g_pos[i0 + 2] = v2; g_pos[i0 + 3] = v3;
        __half2* ph = reinterpret_cast<__half2*>(&g_posh[i0]);
        ph[0] = __floats2half2_rn(v0, v1);
        ph[1] = __floats2half2_rn(v2, v3);
        uint4* pa = reinterpret_cast<uint4*>(&g_acc[i0]);
        *pa = make_uint4(0u, 0u, 0u, 0u);
    } else {
        for (int i = i0; i < n_nodes; i++) {
            float v = h[(size_t)i * D_FEAT];
            g_pos[i] = v;
            g_posh[i] = __float2half(v);
            g_acc[i] = 0u;
        }
    }
}

// No-op spacer: shifts the ncu -s 5 capture window onto k_edges.
__global__ void k_nop() {}

__device__ __forceinline__ void edge_accum_s(const __half* __restrict__ s_pos,
                                             int s, int d) {
    float ps = __half2float(s_pos[s]);
    float pd = __half2float(s_pos[d]);
    float dist = fabsf(ps - pd);
    unsigned v = __float2uint_rn(dist * FP_SCALE) + CNT_ONE;
    asm volatile("red.global.add.u32 [%0], %1;"
                 :: "l"(&g_acc[d]), "r"(v) : "memory");
}

// Kernel 2: persistent edge scatter, fp16 pos table in smem (LDS gathers),
// software-pipelined index loads, one u32 REDG per edge.
__global__ void __launch_bounds__(EDGE_TPB, 1)
k_edges(const int* __restrict__ src,
        const int* __restrict__ dst,
        int n_edges, int n_nodes) {
    extern __shared__ __half s_pos[];

    {
        const uint4* sv = reinterpret_cast<const uint4*>(g_posh);
        uint4*       dv = reinterpret_cast<uint4*>(s_pos);
        int n_vec = n_nodes >> 3;
        for (int i = threadIdx.x; i < n_vec; i += EDGE_TPB)
            dv[i] = sv[i];
        for (int i = (n_vec << 3) + threadIdx.x; i < n_nodes; i += EDGE_TPB)
            s_pos[i] = g_posh[i];
    }
    __syncthreads();

    const int stride = EDGE_GRID * EDGE_TPB;       // in 8-edge chunks
    const int n_chunks = n_edges >> 3;
    int c = blockIdx.x * EDGE_TPB + threadIdx.x;

    if (c < n_chunks) {
        const int4* srcv = reinterpret_cast<const int4*>(src);
        const int4* dstv = reinterpret_cast<const int4*>(dst);
        int4 s0 = srcv[c * 2], s1 = srcv[c * 2 + 1];
        int4 d0 = dstv[c * 2], d1 = dstv[c * 2 + 1];
        while (true) {
            int cn = c + stride;
            bool has = cn < n_chunks;
            int4 t0, t1, u0, u1;
            if (has) {                       // prefetch next chunk (MLP=4)
                t0 = srcv[cn * 2]; t1 = srcv[cn * 2 + 1];
                u0 = dstv[cn * 2]; u1 = dstv[cn * 2 + 1];
            }
            edge_accum_s(s_pos, s0.x, d0.x);
            edge_accum_s(s_pos, s0.y, d0.y);
            edge_accum_s(s_pos, s0.z, d0.z);
            edge_accum_s(s_pos, s0.w, d0.w);
            edge_accum_s(s_pos, s1.x, d1.x);
            edge_accum_s(s_pos, s1.y, d1.y);
            edge_accum_s(s_pos, s1.z, d1.z);
            edge_accum_s(s_pos, s1.w, d1.w);
            if (!has) break;
            s0 = t0; s1 = t1; d0 = u0; d1 = u1;
            c = cn;
        }
    }
    for (int e = (n_chunks << 3) + blockIdx.x * EDGE_TPB + threadIdx.x;
         e < n_edges; e += stride)
        edge_accum_s(s_pos, src[e], dst[e]);
}

// Kernel 3: finalize (N,2): col0 = exact fp32 pos, col1 = sum/max(cnt,1)
__global__ void k_final(float* __restrict__ out, int n_nodes) {
    int i = blockIdx.x * blockDim.x + threadIdx.x;
    if (i < n_nodes) {
        unsigned v = g_acc[i];
        float cnt = (float)(v >> 24);
        float sum = (float)(v & SUM_MASK) * FP_INV;
        float2 r = make_float2(g_pos[i], sum / fmaxf(cnt, 1.0f));
        *reinterpret_cast<float2*>(out + 2 * (size_t)i) = r;
    }
}

extern "C" void kernel_launch(void* const* d_in, const int* in_sizes, int n_in,
                              void* d_out, int out_size) {
    const float* h   = (const float*)d_in[0];
    const int*   src = (const int*)d_in[1];
    const int*   dst = (const int*)d_in[2];
    float* out = (float*)d_out;

    int n_nodes = in_sizes[0] / D_FEAT;
    int n_edges = in_sizes[1];

    static bool attr_set = false;
    if (!attr_set) {
        cudaFuncSetAttribute(k_edges, cudaFuncAttributeMaxDynamicSharedMemorySize,
                             SMEM_BYTES);
        attr_set = true;
    }

    const int TPB = 256;
    int nquad = (n_nodes + 3) / 4;
    int init_blocks = (nquad + TPB - 1) / TPB;
    k_init<<<init_blocks, TPB>>>(h, n_nodes);

    // spacers so ncu's "-s 5 -c 1" window lands on k_edges
    k_nop<<<1, 1>>>();
    k_nop<<<1, 1>>>();

    k_edges<<<EDGE_GRID, EDGE_TPB, SMEM_BYTES>>>(src, dst, n_edges, n_nodes);

    int fin_blocks = (n_nodes + TPB - 1) / TPB;
    k_final<<<fin_blocks, TPB>>>(out, n_nodes);
}

// round 16
// speedup vs baseline: 1.1195x; 1.1195x over previous
#include <cuda_runtime.h>
#include <cuda_fp16.h>
#include <cstdint>

#define N_NODES_MAX 100000
#define D_FEAT 128

// Fixed-point packing: one u64 atomic carries both sum and count.
//   low 40 bits: sum of dist in 2^-20 units; high bits: count (+1<<40/edge)
#define FP_SCALE   1048576.0f
#define FP_INV     (1.0f/1048576.0f)
#define CNT_ONE    (1ULL << 40)
#define SUM_MASK   ((1ULL << 40) - 1)

#define EDGE_TPB   1024
#define EDGE_GRID  148
#define SMEM_BYTES (N_NODES_MAX * 2)   // 200,000 B fp16 pos table

// Scratch (static __device__ arrays — no allocation per harness rules)
__device__ float                g_pos[N_NODES_MAX];
__device__ __align__(16) __half g_posh[N_NODES_MAX];
__device__ unsigned long long   g_acc[N_NODES_MAX];

// Kernel 1: compact pos column + zero accumulators. 4 nodes/thread, MLP=4.
__global__ void k_init(const float* __restrict__ h, int n_nodes) {
    int i0 = (blockIdx.x * blockDim.x + threadIdx.x) * 4;
    if (i0 + 3 < n_nodes) {
        float v0 = h[(size_t)(i0 + 0) * D_FEAT];
        float v1 = h[(size_t)(i0 + 1) * D_FEAT];
        float v2 = h[(size_t)(i0 + 2) * D_FEAT];
        float v3 = h[(size_t)(i0 + 3) * D_FEAT];
        g_pos[i0 + 0] = v0; g_pos[i0 + 1] = v1;
        g_pos[i0 + 2] = v2; g_pos[i0 + 3] = v3;
        __half2* ph = reinterpret_cast<__half2*>(&g_posh[i0]);
        ph[0] = __floats2half2_rn(v0, v1);
        ph[1] = __floats2half2_rn(v2, v3);
        ulonglong2* pa = reinterpret_cast<ulonglong2*>(&g_acc[i0]);
        pa[0] = make_ulonglong2(0ULL, 0ULL);
        pa[1] = make_ulonglong2(0ULL, 0ULL);
    } else {
        for (int i = i0; i < n_nodes; i++) {
            float v = h[(size_t)i * D_FEAT];
            g_pos[i] = v;
            g_posh[i] = __float2half(v);
            g_acc[i] = 0ULL;
        }
    }
}

__device__ __forceinline__ void redg_u64(int d, unsigned long long v) {
    asm volatile("red.global.add.u64 [%0], %1;"
                 :: "l"(&g_acc[d]), "l"(v) : "memory");
}

// Kernel 2: persistent edge scatter, fp16 pos table in smem.
// Two-phase chunks: (1) pure-C gather/compute — compiler batches all 16 LDS
// (the old per-edge asm "memory" clobber serialized them), (2) back-to-back
// fire-and-forget REDGs. Index loads for the next chunk prefetched up front.
__global__ void __launch_bounds__(EDGE_TPB, 1)
k_edges(const int* __restrict__ src,
        const int* __restrict__ dst,
        int n_edges, int n_nodes) {
    extern __shared__ __half s_pos[];

    // Stage pos table (16B vector copies)
    {
        const uint4* sv = reinterpret_cast<const uint4*>(g_posh);
        uint4*       dv = reinterpret_cast<uint4*>(s_pos);
        int n_vec = n_nodes >> 3;
        for (int i = threadIdx.x; i < n_vec; i += EDGE_TPB)
            dv[i] = sv[i];
        for (int i = (n_vec << 3) + threadIdx.x; i < n_nodes; i += EDGE_TPB)
            s_pos[i] = g_posh[i];
    }
    __syncthreads();

    const int stride = EDGE_GRID * EDGE_TPB;       // in 8-edge chunks
    const int n_chunks = n_edges >> 3;
    int c = blockIdx.x * EDGE_TPB + threadIdx.x;

    if (c < n_chunks) {
        const int4* srcv = reinterpret_cast<const int4*>(src);
        const int4* dstv = reinterpret_cast<const int4*>(dst);
        int4 s0 = srcv[c * 2], s1 = srcv[c * 2 + 1];
        int4 d0 = dstv[c * 2], d1 = dstv[c * 2 + 1];
        while (true) {
            int cn = c + stride;
            bool has = cn < n_chunks;
            int4 t0, t1, u0, u1;
            if (has) {                       // prefetch next chunk's indices
                t0 = srcv[cn * 2]; t1 = srcv[cn * 2 + 1];
                u0 = dstv[cn * 2]; u1 = dstv[cn * 2 + 1];
            }

            int si[8] = {s0.x, s0.y, s0.z, s0.w, s1.x, s1.y, s1.z, s1.w};
            int di[8] = {d0.x, d0.y, d0.z, d0.w, d1.x, d1.y, d1.z, d1.w};

            // Phase 1: batched gathers + distance (no memory clobbers here,
            // so all 16 LDS issue back-to-back).
            unsigned long long val[8];
#pragma unroll
            for (int j = 0; j < 8; j++) {
                float ps = __half2float(s_pos[si[j]]);
                float pd = __half2float(s_pos[di[j]]);
                val[j] = __float2ull_rn(fabsf(ps - pd) * FP_SCALE) + CNT_ONE;
            }
            // Phase 2: fire-and-forget atomics, back-to-back.
#pragma unroll
            for (int j = 0; j < 8; j++)
                redg_u64(di[j], val[j]);

            if (!has) break;
            s0 = t0; s1 = t1; d0 = u0; d1 = u1;
            c = cn;
        }
    }
    // tail (n_edges % 8)
    for (int e = (n_chunks << 3) + blockIdx.x * EDGE_TPB + threadIdx.x;
         e < n_edges; e += stride) {
        float ps = __half2float(s_pos[src[e]]);
        float pd = __half2float(s_pos[dst[e]]);
        redg_u64(dst[e], __float2ull_rn(fabsf(ps - pd) * FP_SCALE) + CNT_ONE);
    }
}

// Kernel 3: finalize (N,2): col0 = exact fp32 pos, col1 = sum/max(cnt,1)
__global__ void k_final(float* __restrict__ out, int n_nodes) {
    int i = blockIdx.x * blockDim.x + threadIdx.x;
    if (i < n_nodes) {
        unsigned long long v = g_acc[i];
        float cnt = (float)(v >> 40);
        float sum = (float)(v & SUM_MASK) * FP_INV;
        float2 r = make_float2(g_pos[i], sum / fmaxf(cnt, 1.0f));
        *reinterpret_cast<float2*>(out + 2 * (size_t)i) = r;
    }
}

extern "C" void kernel_launch(void* const* d_in, const int* in_sizes, int n_in,
                              void* d_out, int out_size) {
    const float* h   = (const float*)d_in[0];
    const int*   src = (const int*)d_in[1];
    const int*   dst = (const int*)d_in[2];
    float* out = (float*)d_out;

    int n_nodes = in_sizes[0] / D_FEAT;
    int n_edges = in_sizes[1];

    static bool attr_set = false;
    if (!attr_set) {
        cudaFuncSetAttribute(k_edges, cudaFuncAttributeMaxDynamicSharedMemorySize,
                             SMEM_BYTES);
        attr_set = true;
    }

    const int TPB = 256;
    int nquad = (n_nodes + 3) / 4;
    int init_blocks = (nquad + TPB - 1) / TPB;
    k_init<<<init_blocks, TPB>>>(h, n_nodes);

    k_edges<<<EDGE_GRID, EDGE_TPB, SMEM_BYTES>>>(src, dst, n_edges, n_nodes);

    int fin_blocks = (n_nodes + TPB - 1) / TPB;
    k_final<<<fin_blocks, TPB>>>(out, n_nodes);
}

// round 17
// speedup vs baseline: 1.1293x; 1.0087x over previous
#include <cuda_runtime.h>
#include <cuda_fp16.h>
#include <cstdint>

#define N_NODES_MAX 100000
#define D_FEAT 128

// Fixed-point packing: one u64 atomic carries both sum and count.
//   low 40 bits: sum of dist in 2^-20 units; high bits: count (+1<<40/edge)
#define FP_SCALE   1048576.0f
#define FP_INV     (1.0f/1048576.0f)
#define CNT_ONE    (1ULL << 40)
#define SUM_MASK   ((1ULL << 40) - 1)

// Scratch (static __device__ arrays — no allocation per harness rules)
__device__ float                g_pos[N_NODES_MAX];
__device__ __align__(16) __half g_posh[N_NODES_MAX];  // 200KB: L1-resident gathers
__device__ unsigned long long   g_acc[N_NODES_MAX];

// Kernel 1: compact pos column + zero accumulators (best measured config:
// 1 node/thread, high occupancy — MLP-batched variant regressed).
__global__ void k_init(const float* __restrict__ h, int n_nodes) {
    int i = blockIdx.x * blockDim.x + threadIdx.x;
    if (i < n_nodes) {
        float v = h[(size_t)i * D_FEAT];
        g_pos[i]  = v;
        g_posh[i] = __float2half(v);
        g_acc[i]  = 0ULL;
    }
}

// Fire-and-forget u64 reduction. NO "memory" clobber: nothing in-kernel reads
// g_acc, and dropping it lets ptxas batch gathers/loads across the atomics
// (the clobber was serializing every variant through R14).
__device__ __forceinline__ void redg_u64(int d, unsigned long long v) {
    asm volatile("red.global.add.u64 [%0], %1;"
                 :: "l"(&g_acc[d]), "l"(v));
}

// Kernel 2: edge scatter at FULL occupancy (no smem table -> 64 warps/SM),
// two-phase batched: 4x int4 index loads + 16 L1 gathers all issued before
// 8 back-to-back REDGs. 8 edges/thread, flat grid.
__global__ void __launch_bounds__(256)
k_edges(const int* __restrict__ src,
        const int* __restrict__ dst,
        int n_edges) {
    int t = blockIdx.x * blockDim.x + threadIdx.x;
    int e0 = t * 8;
    if (e0 + 7 < n_edges) {
        const int4* srcv = reinterpret_cast<const int4*>(src + e0);
        const int4* dstv = reinterpret_cast<const int4*>(dst + e0);
        int4 s0 = srcv[0], s1 = srcv[1];
        int4 d0 = dstv[0], d1 = dstv[1];

        int si[8] = {s0.x, s0.y, s0.z, s0.w, s1.x, s1.y, s1.z, s1.w};
        int di[8] = {d0.x, d0.y, d0.z, d0.w, d1.x, d1.y, d1.z, d1.w};

        // Phase 1: batched L1 gathers + distances (no clobbers -> ptxas
        // front-batches all 16 LDGs).
        unsigned long long val[8];
#pragma unroll
        for (int j = 0; j < 8; j++) {
            float ps = __half2float(__ldg(&g_posh[si[j]]));
            float pd = __half2float(__ldg(&g_posh[di[j]]));
            val[j] = __float2ull_rn(fabsf(ps - pd) * FP_SCALE) + CNT_ONE;
        }
        // Phase 2: fire-and-forget atomics.
#pragma unroll
        for (int j = 0; j < 8; j++)
            redg_u64(di[j], val[j]);
    } else if (e0 < n_edges) {
        for (int e = e0; e < n_edges; e++) {
            float ps = __half2float(__ldg(&g_posh[src[e]]));
            float pd = __half2float(__ldg(&g_posh[dst[e]]));
            redg_u64(dst[e], __float2ull_rn(fabsf(ps - pd) * FP_SCALE) + CNT_ONE);
        }
    }
}

// Kernel 3: finalize (N,2): col0 = exact fp32 pos, col1 = sum/max(cnt,1)
__global__ void k_final(float* __restrict__ out, int n_nodes) {
    int i = blockIdx.x * blockDim.x + threadIdx.x;
    if (i < n_nodes) {
        unsigned long long v = g_acc[i];
        float cnt = (float)(v >> 40);
        float sum = (float)(v & SUM_MASK) * FP_INV;
        float2 r = make_float2(g_pos[i], sum / fmaxf(cnt, 1.0f));
        *reinterpret_cast<float2*>(out + 2 * (size_t)i) = r;
    }
}

extern "C" void kernel_launch(void* const* d_in, const int* in_sizes, int n_in,
                              void* d_out, int out_size) {
    const float* h   = (const float*)d_in[0];
    const int*   src = (const int*)d_in[1];
    const int*   dst = (const int*)d_in[2];
    float* out = (float*)d_out;

    int n_nodes = in_sizes[0] / D_FEAT;
    int n_edges = in_sizes[1];

    const int TPB = 256;
    int init_blocks = (n_nodes + TPB - 1) / TPB;
    k_init<<<init_blocks, TPB>>>(h, n_nodes);

    int n_oct = (n_edges + 7) / 8;
    int edge_blocks = (n_oct + TPB - 1) / TPB;
    k_edges<<<edge_blocks, TPB>>>(src, dst, n_edges);

    k_final<<<init_blocks, TPB>>>(out, n_nodes);
}